// round 14
// baseline (speedup 1.0000x reference)
#include <cuda_runtime.h>

#define N 8192
#define ROWS_PER_BLK 256
#define COLS_PER_BLK 256
#define CB 32     /* column tiles: 8192/256 */
#define RB 32     /* row tiles:    8192/256 */
#define THREADS 256
#define EBLK 128  /* epilogue blocks */
#define BAND_TARGET 63   /* blocks with cb==g (32) + rb==g,rb!=cb (31) */

// Scratch (no device allocation allowed -> __device__ globals)
__device__ float g_rowpart[CB * N];     // [cb][row]  partial row sums (1 MiB)
__device__ float g_colpart[RB * N];     // [rb][col]  partial col sums (1 MiB)
__device__ float g_blocksum[EBLK];
__device__ int   g_band_cnt[32];        // per-band producer arrivals
__device__ int   g_cnt_final;           // zero-init; self-resetting

// ---------------------------------------------------------------------------
// Pass 1: one block per 256x256 tile -> 1024 blocks (proven 43.5us loop).
// At block end: release-publish partials and bump the two band counters.
// ---------------------------------------------------------------------------
__global__ void __launch_bounds__(THREADS)
tile_kernel(const float* __restrict__ flow)
{
    const int cb   = blockIdx.x;          // 0..31
    const int rb   = blockIdx.y;          // 0..31
    const int t    = threadIdx.x;         // 0..255
    const int lane = t & 31;
    const int fc   = t & 63;              // float4-col within tile
    const int rsub = t >> 6;              // 0..3
    const int half = (t >> 5) & 1;
    const int row0 = rb * ROWS_PER_BLK;
    const int col0 = cb * COLS_PER_BLK;

    __shared__ float  s_row[ROWS_PER_BLK][8];     // 8 KB
    __shared__ float4 s_cpart[4][64];             // 4 KB

    float4 c0 = make_float4(0.f, 0.f, 0.f, 0.f);

    const float4* base = reinterpret_cast<const float4*>(flow)
                         + (size_t)row0 * (N / 4) + (col0 / 4) + fc;

    #pragma unroll 4
    for (int k = 0; k < ROWS_PER_BLK / 4; ++k) {
        const int r = k * 4 + rsub;
        float4 a = __ldcs(base + (size_t)r * (N / 4));   // streaming

        c0.x += a.x; c0.y += a.y; c0.z += a.z; c0.w += a.w;

        float s = (a.x + a.y) + (a.z + a.w);
        s += __shfl_xor_sync(0xffffffffu, s, 16);
        s += __shfl_xor_sync(0xffffffffu, s, 8);
        s += __shfl_xor_sync(0xffffffffu, s, 4);
        if (lane < 4) s_row[r][half * 4 + lane] = s;
    }

    // Let the dependent (epilogue) grid begin launching while we finish.
    cudaTriggerProgrammaticLaunchCompletion();

    s_cpart[rsub][fc] = c0;
    __syncthreads();

    // Column fold: threads 0..63 fold the 4 rsub partials per float4-col.
    if (t < 64) {
        float4 a0 = s_cpart[0][t], a1 = s_cpart[1][t];
        float4 a2 = s_cpart[2][t], a3 = s_cpart[3][t];
        float4 c;
        c.x = (a0.x + a1.x) + (a2.x + a3.x);
        c.y = (a0.y + a1.y) + (a2.y + a3.y);
        c.z = (a0.z + a1.z) + (a2.z + a3.z);
        c.w = (a0.w + a1.w) + (a2.w + a3.w);
        reinterpret_cast<float4*>(g_colpart + (size_t)rb * N + col0)[t] = c;
    }

    // Row fold: thread r folds its row's 8 partials (fixed order).
    {
        const float* p = s_row[t];
        float s = ((p[0] + p[1]) + (p[2] + p[3]))
                + ((p[4] + p[5]) + (p[6] + p[7]));
        g_rowpart[cb * N + row0 + t] = s;
    }

    // Release-publish: partials visible before the band counters advance.
    __syncthreads();
    __threadfence();
    if (t == 0) {
        atomicAdd(&g_band_cnt[cb], 1);
        if (rb != cb) atomicAdd(&g_band_cnt[rb], 1);
    }
}

// ---------------------------------------------------------------------------
// Pass 2 (PDL epilogue, 128 blocks x 256 threads): block b serves band
// g = b/4 (columns/rows [g*256,(g+1)*256)). Spin-wait (acquire) on the band
// counter instead of a grid-wide dependency -> folds overlap the tile tail.
// Fold structure identical to R13 (bitwise-identical result).
// ---------------------------------------------------------------------------
__global__ void __launch_bounds__(256)
epilogue_kernel(float* __restrict__ out)
{
    const int t   = threadIdx.x;            // 0..255
    const int fcl = t & 15;                 // float4-col within block
    const int sub = t >> 4;                 // 0..15
    const int fc  = blockIdx.x * 16 + fcl;  // global float4-col
    const int g   = blockIdx.x >> 2;        // band

    // acquire: wait until all 63 producers for band g have published
    if (t == 0) {
        while (atomicAdd(&g_band_cnt[g], 0) != BAND_TARGET) __nanosleep(64);
    }
    __syncthreads();
    __threadfence();

    const float4* cp = reinterpret_cast<const float4*>(g_colpart);
    const float4* rp = reinterpret_cast<const float4*>(g_rowpart);

    float4 acc = make_float4(0.f, 0.f, 0.f, 0.f);
    if (sub < 8) {
        #pragma unroll
        for (int j = 0; j < 4; ++j) {
            float4 a = cp[(size_t)(sub * 4 + j) * (N / 4) + fc];
            acc.x += a.x; acc.y += a.y; acc.z += a.z; acc.w += a.w;
        }
    } else {
        #pragma unroll
        for (int j = 0; j < 4; ++j) {
            float4 a = rp[(size_t)((sub - 8) * 4 + j) * (N / 4) + fc];
            acc.x += a.x; acc.y += a.y; acc.z += a.z; acc.w += a.w;
        }
    }

    __shared__ float4 s_part[16][17];       // [sub][fcl] padded
    s_part[sub][fcl] = acc;
    __syncthreads();

    float v = 0.f;
    if (t < 16) {
        float4 cs = make_float4(0.f, 0.f, 0.f, 0.f);
        float4 rs = make_float4(0.f, 0.f, 0.f, 0.f);
        #pragma unroll
        for (int s2 = 0; s2 < 8; ++s2) {
            float4 a = s_part[s2][t];
            cs.x += a.x; cs.y += a.y; cs.z += a.z; cs.w += a.w;
            float4 b = s_part[s2 + 8][t];
            rs.x += b.x; rs.y += b.y; rs.z += b.z; rs.w += b.w;
        }
        v = (fabsf(rs.x - cs.x) + fabsf(rs.y - cs.y))
          + (fabsf(rs.z - cs.z) + fabsf(rs.w - cs.w));
    }

    if (t < 32) {
        v += __shfl_xor_sync(0xffffffffu, v, 8);
        v += __shfl_xor_sync(0xffffffffu, v, 4);
        v += __shfl_xor_sync(0xffffffffu, v, 2);
        v += __shfl_xor_sync(0xffffffffu, v, 1);
        if (t == 0) g_blocksum[blockIdx.x] = v;
    }

    // gate: globally-last block folds the 128 block sums
    __threadfence();
    __syncthreads();
    __shared__ int s_fin;
    if (t == 0) s_fin = (atomicAdd(&g_cnt_final, 1) == EBLK - 1);
    __syncthreads();
    if (!s_fin) return;
    __threadfence();

    float w = (t < EBLK) ? g_blocksum[t] : 0.f;
    w += __shfl_xor_sync(0xffffffffu, w, 16);
    w += __shfl_xor_sync(0xffffffffu, w, 8);
    w += __shfl_xor_sync(0xffffffffu, w, 4);
    w += __shfl_xor_sync(0xffffffffu, w, 2);
    w += __shfl_xor_sync(0xffffffffu, w, 1);

    __shared__ float sw[8];
    if ((t & 31) == 0) sw[t >> 5] = w;
    __syncthreads();

    if (t == 0) {
        float w2 = ((sw[0] + sw[1]) + (sw[2] + sw[3]))
                 + ((sw[4] + sw[5]) + (sw[6] + sw[7]));
        out[0] = w2;
        g_cnt_final = 0;                          // reset for next replay
        #pragma unroll
        for (int k = 0; k < 32; ++k) g_band_cnt[k] = 0;
    }
}

extern "C" void kernel_launch(void* const* d_in, const int* in_sizes, int n_in,
                              void* d_out, int out_size)
{
    (void)in_sizes; (void)n_in; (void)out_size;
    const float* flow = (const float*)d_in[0];
    float* out = (float*)d_out;

    tile_kernel<<<dim3(CB, RB), THREADS>>>(flow);

    // PDL: epilogue blocks may launch while tile_kernel drains; data
    // dependency is enforced by the per-band counters, not the grid edge.
    cudaLaunchConfig_t cfg = {};
    cfg.gridDim  = dim3(EBLK, 1, 1);
    cfg.blockDim = dim3(256, 1, 1);
    cudaLaunchAttribute attr[1];
    attr[0].id = cudaLaunchAttributeProgrammaticStreamSerialization;
    attr[0].val.programmaticStreamSerializationAllowed = 1;
    cfg.attrs = attr;
    cfg.numAttrs = 1;
    cudaLaunchKernelEx(&cfg, epilogue_kernel, out);
}